// round 3
// baseline (speedup 1.0000x reference)
#include <cuda_runtime.h>
#include <math.h>

#define D_DIM 182
#define H_DIM 218
#define W_DIM 182
#define EMBED_DIM 768
#define NREG 117            // REGION_MAX + 1
#define REGION_MAX 116
#define MAX_PTS (1 << 20)

// ---- scratch (static device globals; no allocation) ----
__device__ int g_count[NREG];
__device__ int g_cursor[NREG];
__device__ int g_regid[MAX_PTS];   // region id per point
__device__ int g_sorted[MAX_PTS];  // packed: pt | (region << 24)

// ---------------------------------------------------------------- init
__global__ void init_kernel() {
    int t = threadIdx.x;
    if (t < NREG) g_count[t] = 0;
}

// ---------------------------------------------------------------- region ids + histogram
__global__ __launch_bounds__(256) void region_kernel(
    const float* __restrict__ centers,
    const float* __restrict__ mri,
    const float* __restrict__ aal,
    const float* __restrict__ aal_data,
    int total)
{
    __shared__ float sM[12];
    __shared__ int sHist[NREG];

    const int tid = threadIdx.x;
    if (tid < NREG) sHist[tid] = 0;

    if (tid == 0) {
        // invert aal (4x4 Gauss-Jordan, partial pivot), fuse with mri
        float a[4][8];
        #pragma unroll
        for (int i = 0; i < 4; i++)
            #pragma unroll
            for (int j = 0; j < 4; j++) {
                a[i][j] = aal[i * 4 + j];
                a[i][j + 4] = (i == j) ? 1.0f : 0.0f;
            }
        #pragma unroll
        for (int c = 0; c < 4; c++) {
            int p = c;
            float best = fabsf(a[c][c]);
            for (int r = c + 1; r < 4; r++) {
                float v = fabsf(a[r][c]);
                if (v > best) { best = v; p = r; }
            }
            if (p != c)
                for (int j = 0; j < 8; j++) { float t = a[c][j]; a[c][j] = a[p][j]; a[p][j] = t; }
            float inv = 1.0f / a[c][c];
            for (int j = 0; j < 8; j++) a[c][j] *= inv;
            for (int r = 0; r < 4; r++) {
                if (r == c) continue;
                float f = a[r][c];
                for (int j = 0; j < 8; j++) a[r][j] -= f * a[c][j];
            }
        }
        #pragma unroll
        for (int i = 0; i < 3; i++)
            #pragma unroll
            for (int j = 0; j < 4; j++) {
                float s = 0.0f;
                #pragma unroll
                for (int k = 0; k < 4; k++) s += a[i][k + 4] * mri[k * 4 + j];
                sM[i * 4 + j] = s;
            }
    }
    __syncthreads();

    int pt = blockIdx.x * blockDim.x + tid;
    if (pt < total) {
        float x0 = centers[pt * 3 + 0];
        float y0 = centers[pt * 3 + 1];
        float z0 = centers[pt * 3 + 2];
        float X = sM[0] * x0 + sM[1] * y0 + sM[2]  * z0 + sM[3];
        float Y = sM[4] * x0 + sM[5] * y0 + sM[6]  * z0 + sM[7];
        float Z = sM[8] * x0 + sM[9] * y0 + sM[10] * z0 + sM[11];
        int xi = (int)rintf(X);   // round-half-even, matches jnp.round
        int yi = (int)rintf(Y);
        int zi = (int)rintf(Z);
        bool inb = (xi >= 0) & (xi < D_DIM) & (yi >= 0) & (yi < H_DIM) &
                   (zi >= 0) & (zi < W_DIM);
        int cx = min(max(xi, 0), D_DIM - 1);
        int cy = min(max(yi, 0), H_DIM - 1);
        int cz = min(max(zi, 0), W_DIM - 1);
        int r = (int)__ldg(&aal_data[((size_t)cx * H_DIM + cy) * W_DIM + cz]);
        int region = (inb && r >= 0 && r <= REGION_MAX) ? r : 0;
        g_regid[pt] = region;
        atomicAdd(&sHist[region], 1);
    }
    __syncthreads();
    if (tid < NREG) {
        int c = sHist[tid];
        if (c) atomicAdd(&g_count[tid], c);
    }
}

// ---------------------------------------------------------------- exclusive scan (serial, tiny)
__global__ void scan_kernel() {
    if (threadIdx.x == 0) {
        int run = 0;
        #pragma unroll 1
        for (int i = 0; i < NREG; i++) {
            int c = g_count[i];
            g_cursor[i] = run;
            run += c;
        }
    }
}

// ---------------------------------------------------------------- scatter into sorted order
__global__ __launch_bounds__(256) void scatter_kernel(int total) {
    int pt = blockIdx.x * blockDim.x + threadIdx.x;
    if (pt < total) {
        int r = g_regid[pt];
        int pos = atomicAdd(&g_cursor[r], 1);
        g_sorted[pos] = pt | (r << 24);
    }
}

// ---------------------------------------------------------------- writer: row-reuse stream
#define PTS_PER_WARP 16
#define WTHREADS 256

__global__ __launch_bounds__(WTHREADS) void write_kernel(
    const float* __restrict__ table,
    float* __restrict__ out,
    int total)
{
    const int lane = threadIdx.x & 31;
    const int gw = blockIdx.x * (WTHREADS / 32) + (threadIdx.x >> 5);
    const int start = gw * PTS_PER_WARP;
    if (start >= total) return;
    const int cnt = min(PTS_PER_WARP, total - start);

    // each lane preloads one sorted entry; shfl distributes (no latency in loop)
    int e_mine = (lane < cnt) ? g_sorted[start + lane] : 0;

    int cur = -1;
    float4 r0, r1, r2, r3, r4, r5;

    for (int i = 0; i < cnt; i++) {
        int e = __shfl_sync(0xffffffffu, e_mine, i);
        int region = e >> 24;
        int pt = e & 0xFFFFFF;
        if (region != cur) {
            const float4* __restrict__ src =
                (const float4*)(table + (size_t)region * EMBED_DIM);
            r0 = __ldg(&src[lane]);
            r1 = __ldg(&src[lane + 32]);
            r2 = __ldg(&src[lane + 64]);
            r3 = __ldg(&src[lane + 96]);
            r4 = __ldg(&src[lane + 128]);
            r5 = __ldg(&src[lane + 160]);
            cur = region;
        }
        float4* __restrict__ dst = (float4*)(out + (size_t)pt * EMBED_DIM);
        dst[lane]       = r0;
        dst[lane + 32]  = r1;
        dst[lane + 64]  = r2;
        dst[lane + 96]  = r3;
        dst[lane + 128] = r4;
        dst[lane + 160] = r5;
    }
}

// ---------------------------------------------------------------- launch
extern "C" void kernel_launch(void* const* d_in, const int* in_sizes, int n_in,
                              void* d_out, int out_size) {
    const float* centers = (const float*)d_in[0];  // [B,N,3]
    const float* mri     = (const float*)d_in[1];  // [4,4]
    const float* aal     = (const float*)d_in[2];  // [4,4]
    const float* atlas   = (const float*)d_in[3];  // [D,H,W]
    const float* table   = (const float*)d_in[4];  // [117,768]
    float* out = (float*)d_out;

    int total = in_sizes[0] / 3;

    init_kernel<<<1, 128>>>();
    region_kernel<<<(total + 255) / 256, 256>>>(centers, mri, aal, atlas, total);
    scan_kernel<<<1, 32>>>();
    scatter_kernel<<<(total + 255) / 256, 256>>>(total);

    int nwarps = (total + PTS_PER_WARP - 1) / PTS_PER_WARP;
    int wblocks = (nwarps + (WTHREADS / 32) - 1) / (WTHREADS / 32);
    write_kernel<<<wblocks, WTHREADS>>>(table, out, total);
}

// round 4
// speedup vs baseline: 1.3358x; 1.3358x over previous
#include <cuda_runtime.h>
#include <math.h>

#define D_DIM 182
#define H_DIM 218
#define W_DIM 182
#define EMBED_DIM 768
#define NREG 117
#define REGION_MAX 116
#define MAX_PTS (1 << 20)
#define RBLK 512                         // threads per region/scatter block
#define MAX_BLOCKS (MAX_PTS / RBLK)

// ---- scratch (device globals; no allocation) ----
__device__ int g_tmp[MAX_PTS];                       // region | (localrank << 7)
__device__ int g_sorted[MAX_PTS];                    // pt | (region << 20)
__device__ int g_blockhist[MAX_BLOCKS * NREG];
__device__ int g_blockbase[MAX_BLOCKS * NREG];

// ------------------------------------------------------------ region + hist + local rank
__global__ __launch_bounds__(RBLK) void region_kernel(
    const float* __restrict__ centers,
    const float* __restrict__ mri,
    const float* __restrict__ aal,
    const float* __restrict__ aal_data,
    int total)
{
    __shared__ float sM[12];
    __shared__ int sHist[NREG];

    const int tid = threadIdx.x;
    if (tid < NREG) sHist[tid] = 0;

    if (tid == 0) {
        // invert aal (4x4 Gauss-Jordan, partial pivot), fuse with mri
        float a[4][8];
        #pragma unroll
        for (int i = 0; i < 4; i++)
            #pragma unroll
            for (int j = 0; j < 4; j++) {
                a[i][j] = aal[i * 4 + j];
                a[i][j + 4] = (i == j) ? 1.0f : 0.0f;
            }
        #pragma unroll
        for (int c = 0; c < 4; c++) {
            int p = c;
            float best = fabsf(a[c][c]);
            for (int r = c + 1; r < 4; r++) {
                float v = fabsf(a[r][c]);
                if (v > best) { best = v; p = r; }
            }
            if (p != c)
                for (int j = 0; j < 8; j++) { float t = a[c][j]; a[c][j] = a[p][j]; a[p][j] = t; }
            float inv = 1.0f / a[c][c];
            for (int j = 0; j < 8; j++) a[c][j] *= inv;
            for (int r = 0; r < 4; r++) {
                if (r == c) continue;
                float f = a[r][c];
                for (int j = 0; j < 8; j++) a[r][j] -= f * a[c][j];
            }
        }
        #pragma unroll
        for (int i = 0; i < 3; i++)
            #pragma unroll
            for (int j = 0; j < 4; j++) {
                float s = 0.0f;
                #pragma unroll
                for (int k = 0; k < 4; k++) s += a[i][k + 4] * mri[k * 4 + j];
                sM[i * 4 + j] = s;
            }
    }
    __syncthreads();

    int pt = blockIdx.x * RBLK + tid;
    if (pt < total) {
        float x0 = centers[pt * 3 + 0];
        float y0 = centers[pt * 3 + 1];
        float z0 = centers[pt * 3 + 2];
        float X = sM[0] * x0 + sM[1] * y0 + sM[2]  * z0 + sM[3];
        float Y = sM[4] * x0 + sM[5] * y0 + sM[6]  * z0 + sM[7];
        float Z = sM[8] * x0 + sM[9] * y0 + sM[10] * z0 + sM[11];
        int xi = (int)rintf(X);   // round-half-even, matches jnp.round
        int yi = (int)rintf(Y);
        int zi = (int)rintf(Z);
        bool inb = (xi >= 0) & (xi < D_DIM) & (yi >= 0) & (yi < H_DIM) &
                   (zi >= 0) & (zi < W_DIM);
        int cx = min(max(xi, 0), D_DIM - 1);
        int cy = min(max(yi, 0), H_DIM - 1);
        int cz = min(max(zi, 0), W_DIM - 1);
        int r = (int)__ldg(&aal_data[((size_t)cx * H_DIM + cy) * W_DIM + cz]);
        int region = (inb && r >= 0 && r <= REGION_MAX) ? r : 0;
        int rank = atomicAdd(&sHist[region], 1);        // smem atomic -> local rank
        g_tmp[pt] = region | (rank << 7);
    }
    __syncthreads();
    if (tid < NREG) g_blockhist[blockIdx.x * NREG + tid] = sHist[tid];
}

// ------------------------------------------------------------ scan: per-block bases
__global__ __launch_bounds__(128) void scan_kernel(int nblocks) {
    __shared__ int sTot[NREG];
    const int r = threadIdx.x;

    int run = 0;
    if (r < NREG) {
        #pragma unroll 4
        for (int b = 0; b < nblocks; b++) run += g_blockhist[b * NREG + r];
        sTot[r] = run;
    }
    __syncthreads();
    if (r == 0) {
        int acc = 0;
        #pragma unroll 1
        for (int i = 0; i < NREG; i++) { int c = sTot[i]; sTot[i] = acc; acc += c; }
    }
    __syncthreads();
    if (r < NREG) {
        int base = sTot[r];
        #pragma unroll 4
        for (int b = 0; b < nblocks; b++) {
            int c = g_blockhist[b * NREG + r];
            g_blockbase[b * NREG + r] = base;
            base += c;
        }
    }
}

// ------------------------------------------------------------ scatter (no atomics)
__global__ __launch_bounds__(RBLK) void scatter_kernel(int total) {
    __shared__ int sBase[NREG];
    const int tid = threadIdx.x;
    if (tid < NREG) sBase[tid] = g_blockbase[blockIdx.x * NREG + tid];
    __syncthreads();

    int pt = blockIdx.x * RBLK + tid;
    if (pt < total) {
        int e = g_tmp[pt];
        int region = e & 127;
        int rank = e >> 7;
        g_sorted[sBase[region] + rank] = pt | (region << 20);
    }
}

// ------------------------------------------------------------ writer: row-reuse stream
#define PTS_PER_WARP 16
#define WTHREADS 256

__global__ __launch_bounds__(WTHREADS) void write_kernel(
    const float* __restrict__ table,
    float* __restrict__ out,
    int total)
{
    const int lane = threadIdx.x & 31;
    const int gw = blockIdx.x * (WTHREADS / 32) + (threadIdx.x >> 5);
    const int start = gw * PTS_PER_WARP;
    if (start >= total) return;
    const int cnt = min(PTS_PER_WARP, total - start);

    int e_mine = (lane < cnt) ? g_sorted[start + lane] : 0;

    int cur = -1;
    float4 r0, r1, r2, r3, r4, r5;

    for (int i = 0; i < cnt; i++) {
        int e = __shfl_sync(0xffffffffu, e_mine, i);
        int region = e >> 20;
        int pt = e & 0xFFFFF;
        if (region != cur) {
            const float4* __restrict__ src =
                (const float4*)(table + (size_t)region * EMBED_DIM);
            r0 = __ldg(&src[lane]);
            r1 = __ldg(&src[lane + 32]);
            r2 = __ldg(&src[lane + 64]);
            r3 = __ldg(&src[lane + 96]);
            r4 = __ldg(&src[lane + 128]);
            r5 = __ldg(&src[lane + 160]);
            cur = region;
        }
        float4* __restrict__ dst = (float4*)(out + (size_t)pt * EMBED_DIM);
        dst[lane]       = r0;
        dst[lane + 32]  = r1;
        dst[lane + 64]  = r2;
        dst[lane + 96]  = r3;
        dst[lane + 128] = r4;
        dst[lane + 160] = r5;
    }
}

// ------------------------------------------------------------ launch
extern "C" void kernel_launch(void* const* d_in, const int* in_sizes, int n_in,
                              void* d_out, int out_size) {
    const float* centers = (const float*)d_in[0];
    const float* mri     = (const float*)d_in[1];
    const float* aal     = (const float*)d_in[2];
    const float* atlas   = (const float*)d_in[3];
    const float* table   = (const float*)d_in[4];
    float* out = (float*)d_out;

    int total = in_sizes[0] / 3;
    int nblocks = (total + RBLK - 1) / RBLK;

    region_kernel<<<nblocks, RBLK>>>(centers, mri, aal, atlas, total);
    scan_kernel<<<1, 128>>>(nblocks);
    scatter_kernel<<<nblocks, RBLK>>>(total);

    int nwarps = (total + PTS_PER_WARP - 1) / PTS_PER_WARP;
    int wblocks = (nwarps + (WTHREADS / 32) - 1) / (WTHREADS / 32);
    write_kernel<<<wblocks, WTHREADS>>>(table, out, total);
}

// round 6
// speedup vs baseline: 1.6252x; 1.2167x over previous
#include <cuda_runtime.h>
#include <math.h>
#include <stdint.h>

#define D_DIM 182
#define H_DIM 218
#define W_DIM 182
#define EMBED_DIM 768
#define ROW_BYTES (EMBED_DIM * 4)     // 3072
#define REGION_MAX 116

#define TPB 512
#define PPB 512                        // points per block
#define NDRV 8                         // driver warps
#define SLOTS_PER_DRV (PPB / NDRV)     // 64
#define NBUF 4
// dynamic smem: [0,256)=32 mbarriers, [1024, ...)=NDRV*NBUF row buffers
#define DYN_BUF_OFF 1024
#define DYN_TOTAL (DYN_BUF_OFF + NDRV * NBUF * ROW_BYTES)   // 99328

// ------------------------------------------------------------ ptx helpers
__device__ __forceinline__ uint32_t smem_u32(const void* p) {
    uint32_t a;
    asm("{ .reg .u64 t; cvta.to.shared.u64 t, %1; cvt.u32.u64 %0, t; }"
        : "=r"(a) : "l"(p));
    return a;
}
__device__ __forceinline__ void mbar_init(uint32_t mbar) {
    asm volatile("mbarrier.init.shared.b64 [%0], %1;" :: "r"(mbar), "r"(1) : "memory");
}
__device__ __forceinline__ void mbar_expect_tx(uint32_t mbar, uint32_t bytes) {
    asm volatile("mbarrier.arrive.expect_tx.shared.b64 _, [%0], %1;"
                 :: "r"(mbar), "r"(bytes) : "memory");
}
__device__ __forceinline__ void mbar_wait(uint32_t mbar, uint32_t parity) {
    asm volatile(
        "{\n\t"
        ".reg .pred P;\n\t"
        "LAB_%=:\n\t"
        "mbarrier.try_wait.parity.shared.b64 P, [%0], %1;\n\t"
        "@!P bra LAB_%=;\n\t"
        "}\n"
        :: "r"(mbar), "r"(parity) : "memory");
}
__device__ __forceinline__ void bulk_load(uint32_t dst_smem, const void* src, uint32_t mbar) {
    asm volatile(
        "cp.async.bulk.shared::cluster.global.mbarrier::complete_tx::bytes "
        "[%0], [%1], %2, [%3];"
        :: "r"(dst_smem), "l"(src), "r"((uint32_t)ROW_BYTES), "r"(mbar) : "memory");
}
__device__ __forceinline__ void bulk_store(void* dst, uint32_t src_smem) {
    asm volatile(
        "cp.async.bulk.global.shared::cta.bulk_group [%0], [%1], %2;"
        :: "l"(dst), "r"(src_smem), "r"((uint32_t)ROW_BYTES) : "memory");
}
__device__ __forceinline__ void bulk_commit() {
    asm volatile("cp.async.bulk.commit_group;" ::: "memory");
}
template <int N>
__device__ __forceinline__ void bulk_wait_read() {
    asm volatile("cp.async.bulk.wait_group.read %0;" :: "n"(N) : "memory");
}
template <int N>
__device__ __forceinline__ void bulk_wait_all() {
    asm volatile("cp.async.bulk.wait_group %0;" :: "n"(N) : "memory");
}

// ------------------------------------------------------------ fused kernel
extern __shared__ char dynsmem[];

__global__ __launch_bounds__(TPB, 1) void fused_kernel(
    const float* __restrict__ centers,
    const float* __restrict__ mri,
    const float* __restrict__ aal,
    const float* __restrict__ aal_data,
    const float* __restrict__ table,
    float* __restrict__ out,
    int total)
{
    __shared__ float sM[12];
    __shared__ int sHist[128];
    __shared__ int sScan[128];
    __shared__ int sReg[PPB];
    __shared__ int sPt[PPB];

    const int tid = threadIdx.x;
    const uint32_t dyn_base = smem_u32(dynsmem);

    if (tid < 128) sHist[tid] = 0;
    if (tid < NDRV * NBUF) mbar_init(dyn_base + tid * 8);   // 32 mbarriers

    if (tid == 0) {
        // invert aal (4x4 Gauss-Jordan, partial pivot), fuse with mri
        float a[4][8];
        #pragma unroll
        for (int i = 0; i < 4; i++)
            #pragma unroll
            for (int j = 0; j < 4; j++) {
                a[i][j] = aal[i * 4 + j];
                a[i][j + 4] = (i == j) ? 1.0f : 0.0f;
            }
        #pragma unroll
        for (int c = 0; c < 4; c++) {
            int p = c;
            float best = fabsf(a[c][c]);
            for (int r = c + 1; r < 4; r++) {
                float v = fabsf(a[r][c]);
                if (v > best) { best = v; p = r; }
            }
            if (p != c)
                for (int j = 0; j < 8; j++) { float t = a[c][j]; a[c][j] = a[p][j]; a[p][j] = t; }
            float inv = 1.0f / a[c][c];
            for (int j = 0; j < 8; j++) a[c][j] *= inv;
            for (int r = 0; r < 4; r++) {
                if (r == c) continue;
                float f = a[r][c];
                for (int j = 0; j < 8; j++) a[r][j] -= f * a[c][j];
            }
        }
        #pragma unroll
        for (int i = 0; i < 3; i++)
            #pragma unroll
            for (int j = 0; j < 4; j++) {
                float s = 0.0f;
                #pragma unroll
                for (int k = 0; k < 4; k++) s += a[i][k + 4] * mri[k * 4 + j];
                sM[i * 4 + j] = s;
            }
    }
    __syncthreads();

    // ---- Phase 1: region + local rank
    const int base = blockIdx.x * PPB;
    const int pt = base + tid;
    const bool active = (pt < total);
    int region = 0, rank = 0;
    if (active) {
        float x0 = centers[pt * 3 + 0];
        float y0 = centers[pt * 3 + 1];
        float z0 = centers[pt * 3 + 2];
        float X = sM[0] * x0 + sM[1] * y0 + sM[2]  * z0 + sM[3];
        float Y = sM[4] * x0 + sM[5] * y0 + sM[6]  * z0 + sM[7];
        float Z = sM[8] * x0 + sM[9] * y0 + sM[10] * z0 + sM[11];
        int xi = (int)rintf(X);   // round-half-even, matches jnp.round
        int yi = (int)rintf(Y);
        int zi = (int)rintf(Z);
        bool inb = (xi >= 0) & (xi < D_DIM) & (yi >= 0) & (yi < H_DIM) &
                   (zi >= 0) & (zi < W_DIM);
        int cx = min(max(xi, 0), D_DIM - 1);
        int cy = min(max(yi, 0), H_DIM - 1);
        int cz = min(max(zi, 0), W_DIM - 1);
        int r = (int)__ldg(&aal_data[((size_t)cx * H_DIM + cy) * W_DIM + cz]);
        region = (inb && r >= 0 && r <= REGION_MAX) ? r : 0;
        rank = atomicAdd(&sHist[region], 1);
    }
    __syncthreads();

    // ---- block-local exclusive scan over 128 bins (warp 0)
    if (tid < 32) {
        int c0 = sHist[tid * 4 + 0];
        int c1 = sHist[tid * 4 + 1];
        int c2 = sHist[tid * 4 + 2];
        int c3 = sHist[tid * 4 + 3];
        int sum = c0 + c1 + c2 + c3;
        int incl = sum;
        #pragma unroll
        for (int off = 1; off < 32; off <<= 1) {
            int n = __shfl_up_sync(0xffffffffu, incl, off);
            if (tid >= off) incl += n;
        }
        int excl = incl - sum;
        sScan[tid * 4 + 0] = excl;
        sScan[tid * 4 + 1] = excl + c0;
        sScan[tid * 4 + 2] = excl + c0 + c1;
        sScan[tid * 4 + 3] = excl + c0 + c1 + c2;
    }
    __syncthreads();

    // ---- counting-sort into smem
    if (active) {
        int slot = sScan[region] + rank;
        sReg[slot] = region;
        sPt[slot]  = pt;
    }
    __syncthreads();

    // ---- Phase 2: bulk-copy drivers (one lane per driver warp)
    const int warp = tid >> 5;
    const int lane = tid & 31;
    if (warp < NDRV && lane == 0) {
        const int blockPts = min(PPB, total - base);
        const int s0 = warp * SLOTS_PER_DRV;
        const int s1 = min(s0 + SLOTS_PER_DRV, blockPts);
        if (s0 < s1) {
            // run boundaries
            int starts[SLOTS_PER_DRV + 1];
            int R = 0, prev = -1;
            for (int s = s0; s < s1; s++) {
                int r = sReg[s];
                if (r != prev) { starts[R++] = s; prev = r; }
            }
            starts[R] = s1;

            const uint32_t mbar_base = dyn_base + (uint32_t)warp * NBUF * 8;
            const uint32_t buf_base  = dyn_base + DYN_BUF_OFF +
                                       (uint32_t)warp * NBUF * ROW_BYTES;
            int ph[NBUF] = {0, 0, 0, 0};

            const int pre = (R < NBUF) ? R : NBUF;
            for (int i = 0; i < pre; i++) {
                uint32_t mb = mbar_base + (uint32_t)(i % NBUF) * 8;
                uint32_t bf = buf_base + (uint32_t)(i % NBUF) * ROW_BYTES;
                mbar_expect_tx(mb, ROW_BYTES);
                bulk_load(bf, table + (size_t)sReg[starts[i]] * EMBED_DIM, mb);
            }
            for (int r = 0; r < R; r++) {
                int b = r % NBUF;
                uint32_t mb = mbar_base + (uint32_t)b * 8;
                uint32_t bf = buf_base + (uint32_t)b * ROW_BYTES;
                mbar_wait(mb, ph[b]);
                ph[b] ^= 1;
                for (int s = starts[r]; s < starts[r + 1]; s++)
                    bulk_store(out + (size_t)sPt[s] * EMBED_DIM, bf);
                bulk_commit();
                int nx = r + NBUF;
                if (nx < R) {
                    bulk_wait_read<NBUF - 1>();  // buffer b's readers (group r) done
                    uint32_t mb2 = mbar_base + (uint32_t)(nx % NBUF) * 8;
                    uint32_t bf2 = buf_base + (uint32_t)(nx % NBUF) * ROW_BYTES;
                    mbar_expect_tx(mb2, ROW_BYTES);
                    bulk_load(bf2, table + (size_t)sReg[starts[nx]] * EMBED_DIM, mb2);
                }
            }
            bulk_wait_all<0>();
        }
    }
}

// ------------------------------------------------------------ launch
extern "C" void kernel_launch(void* const* d_in, const int* in_sizes, int n_in,
                              void* d_out, int out_size) {
    const float* centers = (const float*)d_in[0];
    const float* mri     = (const float*)d_in[1];
    const float* aal     = (const float*)d_in[2];
    const float* atlas   = (const float*)d_in[3];
    const float* table   = (const float*)d_in[4];
    float* out = (float*)d_out;

    int total = in_sizes[0] / 3;
    int blocks = (total + PPB - 1) / PPB;

    cudaFuncSetAttribute(fused_kernel,
                         cudaFuncAttributeMaxDynamicSharedMemorySize, DYN_TOTAL);
    fused_kernel<<<blocks, TPB, DYN_TOTAL>>>(centers, mri, aal, atlas, table, out, total);
}

// round 7
// speedup vs baseline: 1.9275x; 1.1860x over previous
#include <cuda_runtime.h>
#include <math.h>

#define D_DIM 182
#define H_DIM 218
#define W_DIM 182
#define EMBED_DIM 768
#define REGION_MAX 116

#define TPB 512
#define PPB 512                       // points per block
#define NWARP (TPB / 32)              // 16
#define SLOTS_PER_WARP (PPB / NWARP)  // 32

__global__ __launch_bounds__(TPB, 1) void fused_kernel(
    const float* __restrict__ centers,
    const float* __restrict__ mri,
    const float* __restrict__ aal,
    const float* __restrict__ aal_data,
    const float* __restrict__ table,
    float* __restrict__ out,
    int total)
{
    __shared__ float sM[12];
    __shared__ int sHist[128];
    __shared__ int sScan[128];
    __shared__ int sReg[PPB];
    __shared__ int sPt[PPB];

    const int tid = threadIdx.x;
    if (tid < 128) sHist[tid] = 0;

    if (tid == 0) {
        // invert aal (4x4 Gauss-Jordan, partial pivot), fuse with mri
        float a[4][8];
        #pragma unroll
        for (int i = 0; i < 4; i++)
            #pragma unroll
            for (int j = 0; j < 4; j++) {
                a[i][j] = aal[i * 4 + j];
                a[i][j + 4] = (i == j) ? 1.0f : 0.0f;
            }
        #pragma unroll
        for (int c = 0; c < 4; c++) {
            int p = c;
            float best = fabsf(a[c][c]);
            for (int r = c + 1; r < 4; r++) {
                float v = fabsf(a[r][c]);
                if (v > best) { best = v; p = r; }
            }
            if (p != c)
                for (int j = 0; j < 8; j++) { float t = a[c][j]; a[c][j] = a[p][j]; a[p][j] = t; }
            float inv = 1.0f / a[c][c];
            for (int j = 0; j < 8; j++) a[c][j] *= inv;
            for (int r = 0; r < 4; r++) {
                if (r == c) continue;
                float f = a[r][c];
                for (int j = 0; j < 8; j++) a[r][j] -= f * a[c][j];
            }
        }
        #pragma unroll
        for (int i = 0; i < 3; i++)
            #pragma unroll
            for (int j = 0; j < 4; j++) {
                float s = 0.0f;
                #pragma unroll
                for (int k = 0; k < 4; k++) s += a[i][k + 4] * mri[k * 4 + j];
                sM[i * 4 + j] = s;
            }
    }
    __syncthreads();

    // ---- Phase 1: region id + block-local rank
    const int base = blockIdx.x * PPB;
    const int pt = base + tid;
    const bool active = (pt < total);
    int region = 0, rank = 0;
    if (active) {
        float x0 = centers[pt * 3 + 0];
        float y0 = centers[pt * 3 + 1];
        float z0 = centers[pt * 3 + 2];
        float X = sM[0] * x0 + sM[1] * y0 + sM[2]  * z0 + sM[3];
        float Y = sM[4] * x0 + sM[5] * y0 + sM[6]  * z0 + sM[7];
        float Z = sM[8] * x0 + sM[9] * y0 + sM[10] * z0 + sM[11];
        int xi = (int)rintf(X);   // round-half-even, matches jnp.round
        int yi = (int)rintf(Y);
        int zi = (int)rintf(Z);
        bool inb = (xi >= 0) & (xi < D_DIM) & (yi >= 0) & (yi < H_DIM) &
                   (zi >= 0) & (zi < W_DIM);
        int cx = min(max(xi, 0), D_DIM - 1);
        int cy = min(max(yi, 0), H_DIM - 1);
        int cz = min(max(zi, 0), W_DIM - 1);
        int r = (int)__ldg(&aal_data[((size_t)cx * H_DIM + cy) * W_DIM + cz]);
        region = (inb && r >= 0 && r <= REGION_MAX) ? r : 0;
        rank = atomicAdd(&sHist[region], 1);
    }
    __syncthreads();

    // ---- block-local exclusive scan over 128 bins (warp 0)
    if (tid < 32) {
        int c0 = sHist[tid * 4 + 0];
        int c1 = sHist[tid * 4 + 1];
        int c2 = sHist[tid * 4 + 2];
        int c3 = sHist[tid * 4 + 3];
        int sum = c0 + c1 + c2 + c3;
        int incl = sum;
        #pragma unroll
        for (int off = 1; off < 32; off <<= 1) {
            int n = __shfl_up_sync(0xffffffffu, incl, off);
            if (tid >= off) incl += n;
        }
        int excl = incl - sum;
        sScan[tid * 4 + 0] = excl;
        sScan[tid * 4 + 1] = excl + c0;
        sScan[tid * 4 + 2] = excl + c0 + c1;
        sScan[tid * 4 + 3] = excl + c0 + c1 + c2;
    }
    __syncthreads();

    // ---- counting sort into smem (region-ordered)
    if (active) {
        int slot = sScan[region] + rank;
        sReg[slot] = region;
        sPt[slot]  = pt;
    }
    __syncthreads();

    // ---- Phase 2: parallel region-run copy. Warp w owns sorted slots [w*32, w*32+32).
    const int warp = tid >> 5;
    const int lane = tid & 31;
    const int blockPts = min(PPB, total - base);
    const int s0 = warp * SLOTS_PER_WARP;
    const int s1 = min(s0 + SLOTS_PER_WARP, blockPts);

    int cur = -1;
    float4 r0, r1, r2, r3, r4, r5;

    for (int s = s0; s < s1; s++) {
        int rg = sReg[s];
        if (rg != cur) {
            const float4* __restrict__ src =
                (const float4*)(table + (size_t)rg * EMBED_DIM);
            r0 = src[lane];
            r1 = src[lane + 32];
            r2 = src[lane + 64];
            r3 = src[lane + 96];
            r4 = src[lane + 128];
            r5 = src[lane + 160];
            cur = rg;
        }
        float4* __restrict__ dst = (float4*)(out + (size_t)sPt[s] * EMBED_DIM);
        dst[lane]       = r0;
        dst[lane + 32]  = r1;
        dst[lane + 64]  = r2;
        dst[lane + 96]  = r3;
        dst[lane + 128] = r4;
        dst[lane + 160] = r5;
    }
}

extern "C" void kernel_launch(void* const* d_in, const int* in_sizes, int n_in,
                              void* d_out, int out_size) {
    const float* centers = (const float*)d_in[0];
    const float* mri     = (const float*)d_in[1];
    const float* aal     = (const float*)d_in[2];
    const float* atlas   = (const float*)d_in[3];
    const float* table   = (const float*)d_in[4];
    float* out = (float*)d_out;

    int total = in_sizes[0] / 3;
    int blocks = (total + PPB - 1) / PPB;

    fused_kernel<<<blocks, TPB>>>(centers, mri, aal, atlas, table, out, total);
}